// round 13
// baseline (speedup 1.0000x reference)
#include <cuda_runtime.h>

#define BB 8
#define TTOT 100
#define NITEMS (BB * TTOT)
#define NN 100000
#define MARGIN_F 0.1f
#define THRESH_F 0.5f
#define NTHREADS 256
#define GRID 592                       // 4/SM * 148 SMs (all resident)

#define NCAX 16
#define NCELLS (NCAX * NCAX * NCAX)    // 4096
#define GRID_LO (-4.0f)
#define CELL_INV 2.0f                  // cell size 0.5
#define SMAX 1024                      // staged points cap (16KB)
#define NUNITS (NCELLS * 4)            // (cell, b-pair)

// Device-global scratch (no allocation). Mutable state is re-initialized in
// Phase A (per launch) or reset by the last block, so graph replays are clean.
__device__ float4       g_retraj[NITEMS];
__device__ float        g_lb[BB][3], g_ub[BB][3];
__device__ unsigned     g_hist[NCELLS], g_cstart[NCELLS], g_ccur[NCELLS];
__device__ unsigned     g_abmin[NCELLS][3], g_abmax[NCELLS][3], g_radkey[NCELLS];
__device__ float        g_lo[NCELLS][3], g_hi[NCELLS][3], g_cw2[NCELLS];
__device__ float4       g_spts[NN];    // sorted (x,y,z, rad+MARGIN)
__device__ int          g_acc[NITEMS];
__device__ unsigned     g_bar1, g_bar2, g_bar3, g_bar4, g_work, g_done;

__device__ __forceinline__ float fast_sqrt(float x) {
    float r;
    asm("sqrt.approx.f32 %0, %1;" : "=f"(r) : "f"(x));
    return r;
}
// Order-preserving float <-> uint for atomic min/max
__device__ __forceinline__ unsigned fenc(float f) {
    unsigned u = __float_as_uint(f);
    return (u & 0x80000000u) ? ~u : (u | 0x80000000u);
}
__device__ __forceinline__ float fdec(unsigned u) {
    unsigned b = (u & 0x80000000u) ? (u ^ 0x80000000u) : ~u;
    return __uint_as_float(b);
}
__device__ __forceinline__ int cell_of(float x, float y, float z) {
    int cx = (int)floorf((x - GRID_LO) * CELL_INV);
    int cy = (int)floorf((y - GRID_LO) * CELL_INV);
    int cz = (int)floorf((z - GRID_LO) * CELL_INV);
    cx = min(max(cx, 0), NCAX - 1);
    cy = min(max(cy, 0), NCAX - 1);
    cz = min(max(cz, 0), NCAX - 1);
    return (cz * NCAX + cy) * NCAX + cx;
}
__device__ __forceinline__ void grid_barrier(unsigned* bar, int tid) {
    __threadfence();
    __syncthreads();
    if (tid == 0) {
        atomicAdd(bar, 1u);
        while (*((volatile unsigned*)bar) < GRID) __nanosleep(64);
    }
    __syncthreads();
    __threadfence();
}

__global__ void __launch_bounds__(NTHREADS, 4) fused_kernel(
    const float* __restrict__ outputs,
    const float* __restrict__ c2ws,
    const float* __restrict__ ss,
    const float* __restrict__ means,
    const float* __restrict__ scales,
    float* __restrict__ out)
{
    const int tid  = threadIdx.x;
    const int lane = tid & 31;
    const int wrp  = tid >> 5;
    const int gi   = blockIdx.x * NTHREADS + tid;
    const int gstr = GRID * NTHREADS;

    // ================= Phase A: init + retrajs + bounds =================
    for (int i = gi; i < NCELLS; i += gstr) {
        g_hist[i] = 0;
        g_radkey[i] = 0;
        #pragma unroll
        for (int e = 0; e < 3; e++) { g_abmin[i][e] = 0xFFFFFFFFu; g_abmax[i][e] = 0; }
    }
    for (int i = gi; i < NITEMS; i += gstr) g_acc[i] = 0;

    if (blockIdx.x < BB) {
        const int b = blockIdx.x;
        __shared__ float4 sh_r[TTOT];
        if (tid < TTOT) {
            const float  sb = ss[b];
            const float* o  = outputs + (b * TTOT + tid) * 3;
            const float* M  = c2ws + b * 16;
            float o0 = o[0], o1 = o[1], o2 = o[2];
            float r0 = fmaf(o0, M[0] * sb, fmaf(o1, M[1] * sb, fmaf(o2, M[2]  * sb, M[3])));
            float r1 = fmaf(o0, M[4] * sb, fmaf(o1, M[5] * sb, fmaf(o2, M[6]  * sb, M[7])));
            float r2 = fmaf(o0, M[8] * sb, fmaf(o1, M[9] * sb, fmaf(o2, M[10] * sb, M[11])));
            float4 v = make_float4(r0, r1, r2, 0.0f);
            g_retraj[b * TTOT + tid] = v;
            sh_r[tid] = v;
        }
        __syncthreads();
        if (wrp < 3) {
            float mn = 1e30f, mx = -1e30f;
            for (int t = lane; t < TTOT; t += 32) {
                float4 rr = sh_r[t];
                float v = (wrp == 0) ? rr.x : ((wrp == 1) ? rr.y : rr.z);
                mn = fminf(mn, v);
                mx = fmaxf(mx, v);
            }
            #pragma unroll
            for (int o = 16; o > 0; o >>= 1) {
                mn = fminf(mn, __shfl_xor_sync(0xffffffffu, mn, o));
                mx = fmaxf(mx, __shfl_xor_sync(0xffffffffu, mx, o));
            }
            if (lane == 0) {
                float thres = THRESH_F * ss[0];
                g_lb[b][wrp] = mn - thres;
                g_ub[b][wrp] = mx + thres;
            }
        }
    }
    grid_barrier(&g_bar1, tid);

    // ================= Phase B1: histogram + cell AABB + max rad =========
    for (int n = gi; n < NN; n += gstr) {
        float x = means[n * 3 + 0], y = means[n * 3 + 1], z = means[n * 3 + 2];
        float s0 = scales[n * 3 + 0], s1 = scales[n * 3 + 1], s2 = scales[n * 3 + 2];
        float rad = fmaxf(s0, fmaxf(s1, s2));
        int c = cell_of(x, y, z);
        atomicAdd(&g_hist[c], 1u);
        atomicMin(&g_abmin[c][0], fenc(x));
        atomicMin(&g_abmin[c][1], fenc(y));
        atomicMin(&g_abmin[c][2], fenc(z));
        atomicMax(&g_abmax[c][0], fenc(x));
        atomicMax(&g_abmax[c][1], fenc(y));
        atomicMax(&g_abmax[c][2], fenc(z));
        atomicMax(&g_radkey[c], fenc(rad));
    }
    grid_barrier(&g_bar2, tid);

    // ================= Phase B2 (block 0): prefix sum + decode ===========
    if (blockIdx.x == 0) {
        __shared__ unsigned ps[NTHREADS];
        unsigned loc[NCELLS / NTHREADS];          // 16 per thread
        unsigned sum = 0;
        #pragma unroll
        for (int k = 0; k < NCELLS / NTHREADS; k++) {
            int c = tid * (NCELLS / NTHREADS) + k;
            loc[k] = sum;
            sum += g_hist[c];
        }
        ps[tid] = sum;
        __syncthreads();
        for (int off = 1; off < NTHREADS; off <<= 1) {
            unsigned v = (tid >= off) ? ps[tid - off] : 0u;
            __syncthreads();
            ps[tid] += v;
            __syncthreads();
        }
        unsigned base = ps[tid] - sum;
        #pragma unroll
        for (int k = 0; k < NCELLS / NTHREADS; k++) {
            int c = tid * (NCELLS / NTHREADS) + k;
            unsigned st = base + loc[k];
            g_cstart[c] = st;
            g_ccur[c]   = st;
            #pragma unroll
            for (int e = 0; e < 3; e++) {
                g_lo[c][e] = fdec(g_abmin[c][e]);
                g_hi[c][e] = fdec(g_abmax[c][e]);
            }
            float cw = fdec(g_radkey[c]) + MARGIN_F;
            g_cw2[c] = cw * cw;
        }
    }
    grid_barrier(&g_bar3, tid);

    // ================= Phase B3: scatter into sorted order ===============
    for (int n = gi; n < NN; n += gstr) {
        float x = means[n * 3 + 0], y = means[n * 3 + 1], z = means[n * 3 + 2];
        float s0 = scales[n * 3 + 0], s1 = scales[n * 3 + 1], s2 = scales[n * 3 + 2];
        float rad = fmaxf(s0, fmaxf(s1, s2));
        int c = cell_of(x, y, z);
        unsigned slot = atomicAdd(&g_ccur[c], 1u);
        g_spts[slot] = make_float4(x, y, z, rad + MARGIN_F);
    }
    grid_barrier(&g_bar4, tid);

    // ================= Phase C: gated evaluation =========================
    __shared__ float4   sh_pts[SMAX];
    __shared__ unsigned sh_list[256];
    __shared__ float    sh_blb[BB][3], sh_bub[BB][3];
    __shared__ unsigned sh_np, sh_next;

    if (tid < BB * 3) {
        int b = tid / 3, e = tid - b * 3;
        sh_blb[b][e] = g_lb[b][e];
        sh_bub[b][e] = g_ub[b][e];
    }
    if (tid == 0) sh_next = atomicAdd(&g_work, 1u);
    int prev_cell = -1;

    for (;;) {
        __syncthreads();                 // eval of previous unit fully done
        unsigned u = sh_next;
        if (tid == 0) sh_np = 0;         // reset gate counter ...
        __syncthreads();                 // ... sequenced BEFORE any atomicAdd
        if (tid == 0) sh_next = atomicAdd(&g_work, 1u);   // prefetch next
        if (u >= NUNITS) break;

        const int cell = u >> 2;
        const int bp   = u & 3;
        const unsigned cnt = g_hist[cell];
        if (cnt == 0) continue;
        const unsigned start = g_cstart[cell];
        const float cw2 = g_cw2[cell];
        const float cl0 = g_lo[cell][0], cl1 = g_lo[cell][1], cl2 = g_lo[cell][2];
        const float ch0 = g_hi[cell][0], ch1 = g_hi[cell][1], ch2 = g_hi[cell][2];
        const int scnt = (cnt < SMAX) ? (int)cnt : SMAX;

        if (cell != prev_cell) {
            prev_cell = cell;
            for (int i = tid; i < scnt; i += NTHREADS)
                sh_pts[i] = g_spts[start + i];
        }
        // Gate: threads 0..99 test b0's t, threads 128..227 test b1's t
        {
            int bl = tid >> 7, tloc = tid & 127;
            if (tloc < TTOT) {
                int b = bp * 2 + bl;
                // cell AABB vs b inside-box intersection (necessary for w > -inf)
                bool isect = (cl0 <= sh_bub[b][0]) & (ch0 >= sh_blb[b][0]) &
                             (cl1 <= sh_bub[b][1]) & (ch1 >= sh_blb[b][1]) &
                             (cl2 <= sh_bub[b][2]) & (ch2 >= sh_blb[b][2]);
                float4 q = g_retraj[b * TTOT + tloc];
                float d0 = fmaxf(fmaxf(cl0 - q.x, q.x - ch0), 0.0f);
                float d1 = fmaxf(fmaxf(cl1 - q.y, q.y - ch1), 0.0f);
                float d2 = fmaxf(fmaxf(cl2 - q.z, q.z - ch2), 0.0f);
                float dm = fmaf(d0, d0, fmaf(d1, d1, d2 * d2));
                if (isect & (dm < cw2)) {
                    unsigned k = atomicAdd(&sh_np, 1u);
                    sh_list[k] = (unsigned)((b << 8) | tloc);
                }
            }
        }
        __syncthreads();
        const int np = (int)sh_np;

        // Each warp takes one passing (b,t); lanes stride the cell's points
        for (int e = wrp; e < np; e += NTHREADS / 32) {
            unsigned v = sh_list[e];
            int b = (int)(v >> 8), t = (int)(v & 255u);
            int item = b * TTOT + t;
            float4 q = g_retraj[item];
            float lb0 = sh_blb[b][0], lb1 = sh_blb[b][1], lb2 = sh_blb[b][2];
            float ub0 = sh_bub[b][0], ub1 = sh_bub[b][1], ub2 = sh_bub[b][2];
            float acc = 0.0f;
            for (int i = lane; i < scnt; i += 32) {
                float4 p = sh_pts[i];
                float dx = q.x - p.x, dy = q.y - p.y, dz = q.z - p.z;
                float d2 = fmaf(dx, dx, fmaf(dy, dy, dz * dz));
                bool ins = (p.x >= lb0) & (p.x <= ub0) &
                           (p.y >= lb1) & (p.y <= ub1) &
                           (p.z >= lb2) & (p.z <= ub2);
                float w = ins ? p.w : -1e30f;
                acc = fmaxf(acc, w - fast_sqrt(d2));
            }
            for (int i = SMAX + lane; i < (int)cnt; i += 32) {   // rare overflow tail
                float4 p = g_spts[start + i];
                float dx = q.x - p.x, dy = q.y - p.y, dz = q.z - p.z;
                float d2 = fmaf(dx, dx, fmaf(dy, dy, dz * dz));
                bool ins = (p.x >= lb0) & (p.x <= ub0) &
                           (p.y >= lb1) & (p.y <= ub1) &
                           (p.z >= lb2) & (p.z <= ub2);
                float w = ins ? p.w : -1e30f;
                acc = fmaxf(acc, w - fast_sqrt(d2));
            }
            #pragma unroll
            for (int o = 16; o > 0; o >>= 1)
                acc = fmaxf(acc, __shfl_xor_sync(0xffffffffu, acc, o));
            if (lane == 0 && acc > 0.0f)
                atomicMax(&g_acc[item], __float_as_int(acc));
        }
    }

    // ============ Last finishing block: final sum + state reset ==========
    __shared__ bool isLast;
    __threadfence();
    if (tid == 0) {
        unsigned prev = atomicAdd(&g_done, 1u);
        isLast = (prev == (unsigned)(GRID - 1));
    }
    __syncthreads();
    if (isLast) {
        __shared__ float sh[NTHREADS];
        float sum = 0.0f;
        for (int i = tid; i < NITEMS; i += NTHREADS)
            sum += __int_as_float(g_acc[i]);
        sh[tid] = sum;
        __syncthreads();
        for (int o = NTHREADS / 2; o > 0; o >>= 1) {
            if (tid < o) sh[tid] += sh[tid + o];
            __syncthreads();
        }
        if (tid == 0) {
            out[0] = sh[0] / (float)NITEMS;
            g_work = 0; g_done = 0;
            g_bar1 = 0; g_bar2 = 0; g_bar3 = 0; g_bar4 = 0;
        }
    }
}

extern "C" void kernel_launch(void* const* d_in, const int* in_sizes, int n_in,
                              void* d_out, int out_size) {
    const float* outputs = (const float*)d_in[0];  // (8,100,3)
    const float* c2ws    = (const float*)d_in[1];  // (8,4,4)
    const float* ss      = (const float*)d_in[2];  // (8,)
    const float* means   = (const float*)d_in[3];  // (100000,3)
    const float* scales  = (const float*)d_in[4];  // (100000,3)
    float* out = (float*)d_out;

    fused_kernel<<<GRID, NTHREADS>>>(outputs, c2ws, ss, means, scales, out);
}

// round 14
// speedup vs baseline: 2.8229x; 2.8229x over previous
#include <cuda_runtime.h>

#define BB 8
#define TTOT 100
#define NITEMS_ACC (BB * TTOT)
#define NN 100000
#define MARGIN_F 0.1f
#define THRESH_F 0.5f
#define T_TILE 10
#define NTT (TTOT / T_TILE)
#define NSPLIT 32
#define NTHREADS 256
#define NWORK (BB * NTT * NSPLIT)      // 2560 work items
#define GRID 444                       // 3/SM * 148 SMs (all resident)
#define PTS_PER_BLK ((NN + GRID - 1) / GRID)   // 226

// Device-global scratch (no allocation). All mutable state is re-initialized
// each launch (Phase A) or reset by the last block, so graph replays are clean.
__device__ float4       g_retraj[NITEMS_ACC];  // (rx,ry,rz,r2)
__device__ float        g_lb[BB][3], g_ub[BB][3];
__device__ float4       g_ctab[BB * NN];       // compacted (-2x,-2y,-2z,m2)
__device__ float        g_cw[BB * NN];         // compacted rad+MARGIN
__device__ unsigned     g_cnt[BB];             // compacted counts
__device__ int          g_acc[NITEMS_ACC];
__device__ unsigned     g_bar1, g_bar2, g_work, g_done;

__device__ __forceinline__ float fast_sqrt(float x) {
    float r;
    asm("sqrt.approx.f32 %0, %1;" : "=f"(r) : "f"(x));
    return r;
}
__device__ __forceinline__ void grid_barrier(unsigned* bar, int tid) {
    __threadfence();
    __syncthreads();
    if (tid == 0) {
        atomicAdd(bar, 1u);
        while (*((volatile unsigned*)bar) < GRID) __nanosleep(64);
    }
    __syncthreads();
    __threadfence();
}

__global__ void __launch_bounds__(NTHREADS, 3) fused_kernel(
    const float* __restrict__ outputs,
    const float* __restrict__ c2ws,
    const float* __restrict__ ss,
    const float* __restrict__ means,
    const float* __restrict__ scales,
    float* __restrict__ out)
{
    const int tid  = threadIdx.x;
    const int lane = tid & 31;
    const int wrp  = tid >> 5;
    const int gi   = blockIdx.x * NTHREADS + tid;
    const int gstr = GRID * NTHREADS;

    // ================= Phase A: init + retrajs + bounds =================
    for (int i = gi; i < NITEMS_ACC; i += gstr) g_acc[i] = 0;
    if (gi < BB) g_cnt[gi] = 0;

    if (blockIdx.x < BB) {
        const int b = blockIdx.x;
        __shared__ float4 sh_r[TTOT];
        if (tid < TTOT) {
            const float  sb = ss[b];
            const float* o  = outputs + (b * TTOT + tid) * 3;
            const float* M  = c2ws + b * 16;
            float o0 = o[0], o1 = o[1], o2 = o[2];
            float r0 = fmaf(o0, M[0] * sb, fmaf(o1, M[1] * sb, fmaf(o2, M[2]  * sb, M[3])));
            float r1 = fmaf(o0, M[4] * sb, fmaf(o1, M[5] * sb, fmaf(o2, M[6]  * sb, M[7])));
            float r2 = fmaf(o0, M[8] * sb, fmaf(o1, M[9] * sb, fmaf(o2, M[10] * sb, M[11])));
            float rr2 = fmaf(r0, r0, fmaf(r1, r1, r2 * r2));
            float4 v = make_float4(r0, r1, r2, rr2);
            g_retraj[b * TTOT + tid] = v;
            sh_r[tid] = v;
        }
        __syncthreads();
        if (wrp < 3) {
            float mn = 1e30f, mx = -1e30f;
            for (int t = lane; t < TTOT; t += 32) {
                float4 rr = sh_r[t];
                float v = (wrp == 0) ? rr.x : ((wrp == 1) ? rr.y : rr.z);
                mn = fminf(mn, v);
                mx = fmaxf(mx, v);
            }
            #pragma unroll
            for (int o = 16; o > 0; o >>= 1) {
                mn = fminf(mn, __shfl_xor_sync(0xffffffffu, mn, o));
                mx = fmaxf(mx, __shfl_xor_sync(0xffffffffu, mx, o));
            }
            if (lane == 0) {
                float thres = THRESH_F * ss[0];
                g_lb[b][wrp] = mn - thres;
                g_ub[b][wrp] = mx + thres;
            }
        }
    }
    grid_barrier(&g_bar1, tid);

    // ===== Phase B: per-b compaction (block-aggregated atomics) =========
    {
        __shared__ float sLB[BB][3], sUB[BB][3];
        __shared__ unsigned s_c[BB], s_base[BB];
        if (tid < BB * 3) {
            int b = tid / 3, e = tid - b * 3;
            sLB[b][e] = g_lb[b][e];
            sUB[b][e] = g_ub[b][e];
        }
        const int p0 = blockIdx.x * PTS_PER_BLK;
        const int p1 = (p0 + PTS_PER_BLK > NN) ? NN : (p0 + PTS_PER_BLK);

        // PTS_PER_BLK (226) <= NTHREADS: single pass
        if (tid < BB) s_c[tid] = 0;
        __syncthreads();

        int n = p0 + tid;
        bool valid = (n < p1);
        float x = 0.f, y = 0.f, z = 0.f, wbase = 0.f, m2 = 0.f;
        unsigned lslot[BB];
        unsigned insmask = 0;
        if (valid) {
            x = means[n * 3 + 0];
            y = means[n * 3 + 1];
            z = means[n * 3 + 2];
            float s0 = scales[n * 3 + 0];
            float s1 = scales[n * 3 + 1];
            float s2 = scales[n * 3 + 2];
            wbase = fmaxf(s0, fmaxf(s1, s2)) + MARGIN_F;
            m2 = fmaf(x, x, fmaf(y, y, z * z));
            #pragma unroll
            for (int b = 0; b < BB; b++) {
                bool ins = (x >= sLB[b][0]) & (x <= sUB[b][0]) &
                           (y >= sLB[b][1]) & (y <= sUB[b][1]) &
                           (z >= sLB[b][2]) & (z <= sUB[b][2]);
                if (ins) {
                    lslot[b] = atomicAdd(&s_c[b], 1u);
                    insmask |= (1u << b);
                }
            }
        }
        __syncthreads();
        if (tid < BB) s_base[tid] = atomicAdd(&g_cnt[tid], s_c[tid]);
        __syncthreads();
        if (valid && insmask) {
            float4 entry = make_float4(-2.0f * x, -2.0f * y, -2.0f * z, m2);
            #pragma unroll
            for (int b = 0; b < BB; b++) {
                if (insmask & (1u << b)) {
                    unsigned slot = s_base[b] + lslot[b];
                    g_ctab[b * NN + slot] = entry;
                    g_cw[b * NN + slot] = wbase;
                }
            }
        }
    }
    grid_barrier(&g_bar2, tid);

    // ===== Phase C: flat eval over compacted per-b lists ================
    __shared__ unsigned sh_item;
    __shared__ float red[T_TILE][NTHREADS / 32];
    for (;;) {
        if (tid == 0) sh_item = atomicAdd(&g_work, 1u);
        __syncthreads();
        unsigned it = sh_item;
        __syncthreads();
        if (it >= NWORK) break;

        const int b  = it / (NTT * NSPLIT);
        const int r_ = it - b * (NTT * NSPLIT);
        const int tt = r_ / NSPLIT;
        const int s  = r_ - tt * NSPLIT;
        const int tbase = tt * T_TILE;

        const int cb = (int)g_cnt[b];
        const int chunk = (cb + NSPLIT - 1) / NSPLIT;
        const int n0 = s * chunk;
        int n1 = n0 + chunk; if (n1 > cb) n1 = cb;

        float rx[T_TILE], ry[T_TILE], rz[T_TILE], C[T_TILE], acc[T_TILE];
        #pragma unroll
        for (int j = 0; j < T_TILE; j++) {
            float4 rr = g_retraj[b * TTOT + tbase + j];
            rx[j] = rr.x; ry[j] = rr.y; rz[j] = rr.z; C[j] = rr.w;
            acc[j] = 0.0f;
        }

        const float4* __restrict__ tab = g_ctab + (size_t)b * NN;
        const float*  __restrict__ wv  = g_cw  + (size_t)b * NN;

        #pragma unroll 2
        for (int n = n0 + tid; n < n1; n += NTHREADS) {
            float4 p = tab[n];
            float  w = wv[n];
            #pragma unroll
            for (int j = 0; j < T_TILE; j++) {
                float d2 = C[j] + p.w;
                d2 = fmaf(p.x, rx[j], d2);
                d2 = fmaf(p.y, ry[j], d2);
                d2 = fmaf(p.z, rz[j], d2);
                // d2<0 only from rounding at dist~0: sqrt->NaN, fmaxf drops it
                float v = w - fast_sqrt(d2);
                acc[j] = fmaxf(acc[j], v);
            }
        }

        #pragma unroll
        for (int j = 0; j < T_TILE; j++) {
            float v = acc[j];
            #pragma unroll
            for (int o = 16; o > 0; o >>= 1)
                v = fmaxf(v, __shfl_xor_sync(0xffffffffu, v, o));
            if (lane == 0) red[j][wrp] = v;
        }
        __syncthreads();
        if (tid < T_TILE) {
            float v = red[tid][0];
            #pragma unroll
            for (int w = 1; w < NTHREADS / 32; w++)
                v = fmaxf(v, red[tid][w]);
            if (v > 0.0f)
                atomicMax(&g_acc[b * TTOT + tbase + tid], __float_as_int(v));
        }
        __syncthreads();
    }

    // ============ Last finishing block: final sum + state reset ==========
    __shared__ bool isLast;
    __threadfence();
    if (tid == 0) {
        unsigned prev = atomicAdd(&g_done, 1u);
        isLast = (prev == (unsigned)(GRID - 1));
    }
    __syncthreads();
    if (isLast) {
        __shared__ float sh[NTHREADS];
        float sum = 0.0f;
        for (int i = tid; i < NITEMS_ACC; i += NTHREADS)
            sum += __int_as_float(g_acc[i]);
        sh[tid] = sum;
        __syncthreads();
        for (int o = NTHREADS / 2; o > 0; o >>= 1) {
            if (tid < o) sh[tid] += sh[tid + o];
            __syncthreads();
        }
        if (tid == 0) {
            out[0] = sh[0] / (float)NITEMS_ACC;
            g_work = 0; g_done = 0;
            g_bar1 = 0; g_bar2 = 0;
        }
    }
}

extern "C" void kernel_launch(void* const* d_in, const int* in_sizes, int n_in,
                              void* d_out, int out_size) {
    const float* outputs = (const float*)d_in[0];  // (8,100,3)
    const float* c2ws    = (const float*)d_in[1];  // (8,4,4)
    const float* ss      = (const float*)d_in[2];  // (8,)
    const float* means   = (const float*)d_in[3];  // (100000,3)
    const float* scales  = (const float*)d_in[4];  // (100000,3)
    float* out = (float*)d_out;

    fused_kernel<<<GRID, NTHREADS>>>(outputs, c2ws, ss, means, scales, out);
}